// round 1
// baseline (speedup 1.0000x reference)
#include <cuda_runtime.h>
#include <math.h>

#define Bv 8
#define Cv 64
#define Hv 128
#define Wv 128
#define Ov 64
#define HWv (Hv*Wv)

// scratch (allocation-free rule: __device__ globals)
__device__ float g_offset[Bv*18*HWv];   // (B,18,H,W)
__device__ float g_mask[Bv*9*HWv];      // (B,9,H,W)
__device__ float g_mean[Ov];
__device__ float g_rstd[Ov];

// ---------------------------------------------------------------------------
// offset = conv(1x15, pad_w=7) + conv(15x1, pad_h=7), 18 output channels
// ---------------------------------------------------------------------------
__global__ void offset_kernel(const float* __restrict__ x,
                              const float* __restrict__ wh, const float* __restrict__ bh,
                              const float* __restrict__ wv, const float* __restrict__ bv) {
    int idx = blockIdx.x * blockDim.x + threadIdx.x;
    if (idx >= Bv*18*HWv) return;
    int w = idx & (Wv-1);
    int h = (idx >> 7) & (Hv-1);
    int o = (idx / HWv) % 18;
    int b = idx / (18*HWv);

    float acc = bh[o] + bv[o];
    const float* xb = x + (size_t)b*Cv*HWv;
    for (int c = 0; c < Cv; c++) {
        const float* xc   = xb + c*HWv;
        const float* whp  = wh + (o*Cv + c)*15;
        const float* wvp  = wv + (o*Cv + c)*15;
        const float* xrow = xc + h*Wv;
        #pragma unroll
        for (int k = 0; k < 15; k++) {
            int ww = w + k - 7;
            if (ww >= 0 && ww < Wv) acc = fmaf(xrow[ww], whp[k], acc);
        }
        #pragma unroll
        for (int k = 0; k < 15; k++) {
            int hh = h + k - 7;
            if (hh >= 0 && hh < Hv) acc = fmaf(xc[hh*Wv + w], wvp[k], acc);
        }
    }
    g_offset[idx] = acc;
}

// ---------------------------------------------------------------------------
// mask = sigmoid(conv3x3(x, wm) + bm), 9 output channels
// ---------------------------------------------------------------------------
__global__ void mask_kernel(const float* __restrict__ x,
                            const float* __restrict__ wm, const float* __restrict__ bm) {
    int idx = blockIdx.x * blockDim.x + threadIdx.x;
    if (idx >= Bv*9*HWv) return;
    int w = idx & (Wv-1);
    int h = (idx >> 7) & (Hv-1);
    int o = (idx / HWv) % 9;
    int b = idx / (9*HWv);

    float acc = bm[o];
    const float* xb = x + (size_t)b*Cv*HWv;
    for (int c = 0; c < Cv; c++) {
        const float* xc = xb + c*HWv;
        const float* wp = wm + (o*Cv + c)*9;
        #pragma unroll
        for (int ky = 0; ky < 3; ky++) {
            int hh = h + ky - 1;
            if (hh < 0 || hh >= Hv) continue;
            #pragma unroll
            for (int kx = 0; kx < 3; kx++) {
                int ww = w + kx - 1;
                if (ww >= 0 && ww < Wv)
                    acc = fmaf(xc[hh*Wv + ww], wp[ky*3 + kx], acc);
            }
        }
    }
    g_mask[idx] = 1.0f / (1.0f + expf(-acc));
}

// ---------------------------------------------------------------------------
// deformable conv: 16 pixels per block, shared sampled tensor, GEMV per pixel
// ---------------------------------------------------------------------------
#define TILE 16
__global__ void __launch_bounds__(128) deform_kernel(const float* __restrict__ x,
                                                     const float* __restrict__ wd,
                                                     float* __restrict__ out) {
    __shared__ float s[TILE*576];       // s[p*576 + c*9 + k]
    __shared__ float sdy[TILE*9], sdx[TILE*9], smk[TILE*9];

    int tid = threadIdx.x;
    int b  = blockIdx.z;
    int h  = blockIdx.y;
    int w0 = blockIdx.x * TILE;

    for (int e = tid; e < TILE*9; e += 128) {
        int p = e / 9, k = e - p*9;
        int w = w0 + p;
        sdy[e] = g_offset[((b*18 + 2*k  )*Hv + h)*Wv + w];
        sdx[e] = g_offset[((b*18 + 2*k+1)*Hv + h)*Wv + w];
        smk[e] = g_mask  [((b*9  + k   )*Hv + h)*Wv + w];
    }
    __syncthreads();

    const float* xb = x + (size_t)b*Cv*HWv;
    for (int e = tid; e < TILE*576; e += 128) {
        int p = e / 576;
        int r = e - p*576;
        int c = r / 9;
        int k = r - c*9;
        int ky = k / 3, kx = k - ky*3;
        int pk = p*9 + k;

        float py = (float)(h + ky - 1) + sdy[pk];
        float px = (float)(w0 + p + kx - 1) + sdx[pk];
        float y0f = floorf(py), x0f = floorf(px);
        int   y0  = (int)y0f,   x0  = (int)x0f;
        float wy1 = py - y0f, wx1 = px - x0f;
        float wy0 = 1.0f - wy1, wx0 = 1.0f - wx1;

        bool vy0 = (y0 >= 0)  && (y0 < Hv);
        bool vy1 = (y0 >= -1) && (y0 < Hv-1);
        bool vx0 = (x0 >= 0)  && (x0 < Wv);
        bool vx1 = (x0 >= -1) && (x0 < Wv-1);

        const float* img = xb + c*HWv;
        float v = 0.0f;
        if (vy0 && vx0) v = fmaf(img[y0*Wv + x0],       wy0*wx0, v);
        if (vy0 && vx1) v = fmaf(img[y0*Wv + x0 + 1],   wy0*wx1, v);
        if (vy1 && vx0) v = fmaf(img[(y0+1)*Wv + x0],   wy1*wx0, v);
        if (vy1 && vx1) v = fmaf(img[(y0+1)*Wv + x0+1], wy1*wx1, v);
        s[e] = v * smk[pk];
    }
    __syncthreads();

    // phase 2: GEMV. o = tid%64; two warps-pairs split the 16 pixels.
    int o    = tid & 63;
    int half = tid >> 6;                 // 0 -> pixels 0..7, 1 -> pixels 8..15
    const float* wrow  = wd + o*576;
    const float* sbase = s + half*8*576;
    float acc[8];
    #pragma unroll
    for (int p = 0; p < 8; p++) acc[p] = 0.0f;
    for (int j = 0; j < 576; j++) {
        float wvl = wrow[j];
        #pragma unroll
        for (int p = 0; p < 8; p++)
            acc[p] = fmaf(sbase[p*576 + j], wvl, acc[p]);
    }
    float* orow = out + (((size_t)b*Ov + o)*Hv + h)*Wv + w0 + half*8;
    #pragma unroll
    for (int p = 0; p < 8; p++) orow[p] = acc[p];
}

// ---------------------------------------------------------------------------
// BN stats: one block per channel
// ---------------------------------------------------------------------------
__global__ void reduce_kernel(const float* __restrict__ y) {
    int c = blockIdx.x;
    int tid = threadIdx.x;
    float sum = 0.0f, sq = 0.0f;
    for (int i = tid; i < Bv*HWv; i += 256) {
        int b = i >> 14;             // HW = 16384
        int r = i & (HWv - 1);
        float v = y[((size_t)b*Ov + c)*HWv + r];
        sum += v;
        sq   = fmaf(v, v, sq);
    }
    __shared__ float ssum[256], ssq[256];
    ssum[tid] = sum; ssq[tid] = sq;
    __syncthreads();
    for (int off = 128; off > 0; off >>= 1) {
        if (tid < off) { ssum[tid] += ssum[tid+off]; ssq[tid] += ssq[tid+off]; }
        __syncthreads();
    }
    if (tid == 0) {
        const float inv_n = 1.0f / (float)(Bv*HWv);
        float mean = ssum[0] * inv_n;
        float var  = ssq[0] * inv_n - mean*mean;
        g_mean[c] = mean;
        g_rstd[c] = rsqrtf(var + 1e-5f);
    }
}

__global__ void bn_kernel(float* __restrict__ y,
                          const float* __restrict__ gamma,
                          const float* __restrict__ beta) {
    int idx = blockIdx.x * blockDim.x + threadIdx.x;
    if (idx >= Bv*Ov*HWv) return;
    int c = (idx / HWv) % Ov;
    float v = (y[idx] - g_mean[c]) * g_rstd[c] * gamma[c] + beta[c];
    y[idx] = v > 0.0f ? v : 0.0f;
}

// ---------------------------------------------------------------------------
extern "C" void kernel_launch(void* const* d_in, const int* in_sizes, int n_in,
                              void* d_out, int out_size) {
    const float* x     = (const float*)d_in[0];
    const float* wh    = (const float*)d_in[1];
    const float* bh    = (const float*)d_in[2];
    const float* wv    = (const float*)d_in[3];
    const float* bv    = (const float*)d_in[4];
    const float* wm    = (const float*)d_in[5];
    const float* bm    = (const float*)d_in[6];
    const float* wd    = (const float*)d_in[7];
    const float* gamma = (const float*)d_in[8];
    const float* beta  = (const float*)d_in[9];
    float* out = (float*)d_out;

    offset_kernel<<<(Bv*18*HWv + 255)/256, 256>>>(x, wh, bh, wv, bv);
    mask_kernel  <<<(Bv*9*HWv  + 255)/256, 256>>>(x, wm, bm);

    dim3 grid(Wv/TILE, Hv, Bv);
    deform_kernel<<<grid, 128>>>(x, wd, out);

    reduce_kernel<<<Ov, 256>>>(out);
    bn_kernel    <<<(Bv*Ov*HWv + 255)/256, 256>>>(out, gamma, beta);
}

// round 3
// speedup vs baseline: 3.1776x; 3.1776x over previous
#include <cuda_runtime.h>
#include <math.h>

#define Bv 8
#define Cv 64
#define Hv 128
#define Wv 128
#define Ov 64
#define HWv (Hv*Wv)

// scratch (__device__ globals; no allocation allowed)
__device__ float g_offset[Bv*18*HWv];   // (B,18,H,W)
__device__ float g_mask[Bv*9*HWv];      // (B,9,H,W)
__device__ float g_xt[(size_t)Bv*HWv*Cv]; // (B,H,W,C)
__device__ float g_whP[Cv*18*16];
__device__ float g_wvP[Cv*18*16];
__device__ float g_wmP[Cv*9*12];
__device__ float g_wdT[Ov*576];         // [o][k*64+c]
__device__ float g_psum[Ov*Bv];
__device__ float g_psq[Ov*Bv];
__device__ float g_mean[Ov];
__device__ float g_rstd[Ov];

// ---------------------------------------------------------------------------
// weight packer
// ---------------------------------------------------------------------------
__global__ void pack_kernel(const float* __restrict__ wh, const float* __restrict__ wv,
                            const float* __restrict__ wm, const float* __restrict__ wd) {
    int idx = blockIdx.x*256 + threadIdx.x;
    if (idx < 18432) {
        int c = idx/288, r = idx - c*288, o = r >> 4, k = r & 15;
        g_whP[idx] = (k < 15) ? wh[(o*Cv + c)*15 + k] : 0.f;
        g_wvP[idx] = (k < 15) ? wv[(o*Cv + c)*15 + k] : 0.f;
    } else if (idx < 18432 + 6912) {
        int j = idx - 18432;
        int c = j/108, r = j - c*108, o = r/12, k = r - o*12;
        g_wmP[j] = (k < 9) ? wm[(o*Cv + c)*9 + k] : 0.f;
    } else if (idx < 18432 + 6912 + 36864) {
        int j = idx - 18432 - 6912;
        int o = j/576, r = j - o*576, k = r >> 6, c = r & 63;
        g_wdT[j] = wd[(o*Cv + c)*9 + k];
    }
}

// ---------------------------------------------------------------------------
// x (B,C,HW) -> xt (B,HW,C)
// ---------------------------------------------------------------------------
__global__ void transpose_kernel(const float* __restrict__ x) {
    __shared__ float t[32][33];
    int b = blockIdx.z;
    int hw0 = blockIdx.x * 32;
    int c0  = blockIdx.y * 32;
    int tx = threadIdx.x, ty = threadIdx.y;
    #pragma unroll
    for (int j = 0; j < 4; j++) {
        int c = c0 + ty + j*8;
        t[ty + j*8][tx] = x[((size_t)b*Cv + c)*HWv + hw0 + tx];
    }
    __syncthreads();
    #pragma unroll
    for (int j = 0; j < 4; j++) {
        int hw = hw0 + ty + j*8;
        g_xt[((size_t)b*HWv + hw)*Cv + c0 + tx] = t[tx][ty + j*8];
    }
}

// ---------------------------------------------------------------------------
// fused offset(18ch: 1x15 + 15x1) + mask(9ch: 3x3 + sigmoid)
// tile 32x8 pixels, 128 threads, 2 pixels/thread
// ---------------------------------------------------------------------------
__global__ void __launch_bounds__(128, 3) offmask_kernel(
    const float* __restrict__ x,
    const float* __restrict__ bh, const float* __restrict__ bv,
    const float* __restrict__ bm)
{
    __shared__ float tile[22*47];
    int b  = blockIdx.z;
    int h0 = blockIdx.y * 8;
    int wb = blockIdx.x * 32;
    int tid = threadIdx.x;
    int tx = tid & 15, ty = tid >> 4;
    int h = h0 + ty;
    int w = wb + 2*tx;

    float acc0[18], acc1[18], am0[9], am1[9];
    #pragma unroll
    for (int o = 0; o < 18; o++) { float bo = bh[o] + bv[o]; acc0[o] = bo; acc1[o] = bo; }
    #pragma unroll
    for (int o = 0; o < 9; o++)  { float bo = bm[o]; am0[o] = bo; am1[o] = bo; }

    const float* xb = x + (size_t)b*Cv*HWv;
    for (int c = 0; c < Cv; c++) {
        __syncthreads();
        const float* xc = xb + c*HWv;
        for (int i = tid; i < 22*46; i += 128) {
            int r = i / 46, cc = i - r*46;
            int gh = h0 + r - 7, gw = wb + cc - 7;
            float v = 0.f;
            if (gh >= 0 && gh < Hv && gw >= 0 && gw < Wv) v = xc[gh*Wv + gw];
            tile[r*47 + cc] = v;
        }
        __syncthreads();

        float xr[16];
        #pragma unroll
        for (int i = 0; i < 16; i++) xr[i] = tile[(ty+7)*47 + 2*tx + i];
        float xcA[15], xcB[15];
        #pragma unroll
        for (int i = 0; i < 15; i++) {
            xcA[i] = tile[(ty+i)*47 + 2*tx + 7];
            xcB[i] = tile[(ty+i)*47 + 2*tx + 8];
        }
        float t00 = tile[(ty+6)*47 + 2*tx + 6];
        float t01 = tile[(ty+6)*47 + 2*tx + 9];
        float t10 = tile[(ty+8)*47 + 2*tx + 6];
        float t11 = tile[(ty+8)*47 + 2*tx + 9];

        const float4* whc = (const float4*)(g_whP + c*288);
        const float4* wvc = (const float4*)(g_wvP + c*288);
        const float4* wmc = (const float4*)(g_wmP + c*108);
        #pragma unroll
        for (int o = 0; o < 18; o++) {
            float4 q0 = whc[o*4+0], q1 = whc[o*4+1], q2 = whc[o*4+2], q3 = whc[o*4+3];
            float wkh[15] = {q0.x,q0.y,q0.z,q0.w, q1.x,q1.y,q1.z,q1.w,
                             q2.x,q2.y,q2.z,q2.w, q3.x,q3.y,q3.z};
            float a0 = acc0[o], a1 = acc1[o];
            #pragma unroll
            for (int k = 0; k < 15; k++) {
                a0 = fmaf(xr[k],   wkh[k], a0);
                a1 = fmaf(xr[k+1], wkh[k], a1);
            }
            float4 v0 = wvc[o*4+0], v1 = wvc[o*4+1], v2 = wvc[o*4+2], v3 = wvc[o*4+3];
            float wkv[15] = {v0.x,v0.y,v0.z,v0.w, v1.x,v1.y,v1.z,v1.w,
                             v2.x,v2.y,v2.z,v2.w, v3.x,v3.y,v3.z};
            #pragma unroll
            for (int k = 0; k < 15; k++) {
                a0 = fmaf(xcA[k], wkv[k], a0);
                a1 = fmaf(xcB[k], wkv[k], a1);
            }
            acc0[o] = a0; acc1[o] = a1;
        }
        #pragma unroll
        for (int o = 0; o < 9; o++) {
            float4 q0 = wmc[o*3], q1 = wmc[o*3+1], q2 = wmc[o*3+2];
            float m0 = am0[o], m1 = am1[o];
            m0 = fmaf(t00,    q0.x, m0);  m1 = fmaf(xcA[6], q0.x, m1);
            m0 = fmaf(xcA[6], q0.y, m0);  m1 = fmaf(xcB[6], q0.y, m1);
            m0 = fmaf(xcB[6], q0.z, m0);  m1 = fmaf(t01,    q0.z, m1);
            m0 = fmaf(xr[6],  q0.w, m0);  m1 = fmaf(xr[7],  q0.w, m1);
            m0 = fmaf(xr[7],  q1.x, m0);  m1 = fmaf(xr[8],  q1.x, m1);
            m0 = fmaf(xr[8],  q1.y, m0);  m1 = fmaf(xr[9],  q1.y, m1);
            m0 = fmaf(t10,    q1.z, m0);  m1 = fmaf(xcA[8], q1.z, m1);
            m0 = fmaf(xcA[8], q1.w, m0);  m1 = fmaf(xcB[8], q1.w, m1);
            m0 = fmaf(xcB[8], q2.x, m0);  m1 = fmaf(t11,    q2.x, m1);
            am0[o] = m0; am1[o] = m1;
        }
    }

    #pragma unroll
    for (int o = 0; o < 18; o++) {
        float2 v; v.x = acc0[o]; v.y = acc1[o];
        *(float2*)&g_offset[((b*18 + o)*Hv + h)*Wv + w] = v;
    }
    #pragma unroll
    for (int o = 0; o < 9; o++) {
        float2 v;
        v.x = 1.f/(1.f + __expf(-am0[o]));
        v.y = 1.f/(1.f + __expf(-am1[o]));
        *(float2*)&g_mask[((b*9 + o)*Hv + h)*Wv + w] = v;
    }
}

// ---------------------------------------------------------------------------
// deform: per 16-pixel tile: stage A (144 interp setups), stage B (HWC gather
// -> s[16][576] in smem), stage C (64x576x16 GEMM from smem weights)
// stage C: warp = 2 output channels x 16 pixels -> near-broadcast weight LDS
// ---------------------------------------------------------------------------
#define SW_STRIDE 580
#define SS_STRIDE 580
__global__ void __launch_bounds__(256, 1) deform_kernel(float* __restrict__ out) {
    extern __shared__ float smem[];
    float* sw = smem;                         // 64*SW_STRIDE
    float* ss = smem + 64*SW_STRIDE;          // 16*SS_STRIDE
    int*  sAy = (int*)(ss + 16*SS_STRIDE);    // 144
    int*  sAx = sAy + 144;                    // 144
    float4* sAw = (float4*)(sAx + 144);       // 144
    int tid = threadIdx.x;

    const float4* wt4 = (const float4*)g_wdT;
    for (int i = tid; i < 64*144; i += 256) {
        int o = i / 144, q = i - o*144;
        ((float4*)(sw + o*SW_STRIDE))[q] = wt4[i];
    }

    int rem = blockIdx.x;
    int h  = rem >> 3;
    int w0 = (rem & 7) << 4;

    for (int b = 0; b < Bv; b++) {
        __syncthreads();   // weights ready / prev stage C reads done
        if (tid < 144) {
            int p = tid / 9, k = tid - p*9;
            int w = w0 + p;
            int ky = k / 3, kx = k - ky*3;
            float dy = g_offset[((b*18 + 2*k    )*Hv + h)*Wv + w];
            float dx = g_offset[((b*18 + 2*k + 1)*Hv + h)*Wv + w];
            float m  = g_mask  [((b*9  + k      )*Hv + h)*Wv + w];
            float py = (float)(h + ky - 1) + dy;
            float px = (float)(w + kx - 1) + dx;
            float y0f = floorf(py), x0f = floorf(px);
            float wy1 = py - y0f, wx1 = px - x0f;
            float wy0 = 1.f - wy1, wx0 = 1.f - wx1;
            int iy0 = (int)y0f, ix0 = (int)x0f;
            bool vy0 = (iy0 >= 0)  && (iy0 < Hv);
            bool vy1 = (iy0 >= -1) && (iy0 < Hv-1);
            bool vx0 = (ix0 >= 0)  && (ix0 < Wv);
            bool vx1 = (ix0 >= -1) && (ix0 < Wv-1);
            sAy[tid] = iy0; sAx[tid] = ix0;
            sAw[tid] = make_float4((vy0 && vx0) ? m*wy0*wx0 : 0.f,
                                   (vy0 && vx1) ? m*wy0*wx1 : 0.f,
                                   (vy1 && vx0) ? m*wy1*wx0 : 0.f,
                                   (vy1 && vx1) ? m*wy1*wx1 : 0.f);
        }
        __syncthreads();

        const float4* xb4 = (const float4*)g_xt + (size_t)b*HWv*16;
        #pragma unroll
        for (int itb = 0; itb < 9; itb++) {
            int it = itb*256 + tid;       // 0..2303
            int pk = it >> 4, cq = it & 15;
            int iy0 = sAy[pk], ix0 = sAx[pk];
            float4 wg = sAw[pk];
            int y0c = min(Hv-1, max(0, iy0));
            int y1c = min(Hv-1, max(0, iy0 + 1));
            int x0c = min(Wv-1, max(0, ix0));
            int x1c = min(Wv-1, max(0, ix0 + 1));
            float4 v00 = xb4[(y0c*Wv + x0c)*16 + cq];
            float4 v01 = xb4[(y0c*Wv + x1c)*16 + cq];
            float4 v10 = xb4[(y1c*Wv + x0c)*16 + cq];
            float4 v11 = xb4[(y1c*Wv + x1c)*16 + cq];
            float4 r;
            r.x = fmaf(wg.w, v11.x, fmaf(wg.z, v10.x, fmaf(wg.y, v01.x, wg.x*v00.x)));
            r.y = fmaf(wg.w, v11.y, fmaf(wg.z, v10.y, fmaf(wg.y, v01.y, wg.x*v00.y)));
            r.z = fmaf(wg.w, v11.z, fmaf(wg.z, v10.z, fmaf(wg.y, v01.z, wg.x*v00.z)));
            r.w = fmaf(wg.w, v11.w, fmaf(wg.z, v10.w, fmaf(wg.y, v01.w, wg.x*v00.w)));
            int p = pk / 9, k = pk - p*9;
            ((float4*)(ss + p*SS_STRIDE))[k*16 + cq] = r;
        }
        __syncthreads();

        // stage C: warp wi handles o in {2*wi, 2*wi+16, 2*wi+32, 2*wi+48}? No:
        // warp wi (0..7) covers o0 = wi*8 .. wi*8+7 via lane>>4 selecting o pair.
        // thread: pixel p = lane&15, o = wi*8 + (lane>>4)*4 + j  (j=0..3)
        {
            int lane = tid & 31, wi = tid >> 5;
            int p  = lane & 15;
            int ob = wi*8 + (lane >> 4)*4;    // 4 consecutive o's per thread
            const float4* sp = (const float4*)(ss + p*SS_STRIDE);
            const float4* w0p = (const float4*)(sw + (ob+0)*SW_STRIDE);
            const float4* w1p = (const float4*)(sw + (ob+1)*SW_STRIDE);
            const float4* w2p = (const float4*)(sw + (ob+2)*SW_STRIDE);
            const float4* w3p = (const float4*)(sw + (ob+3)*SW_STRIDE);
            float a0 = 0.f, a1 = 0.f, a2 = 0.f, a3 = 0.f;
            #pragma unroll 4
            for (int jq = 0; jq < 144; jq++) {
                float4 sv = sp[jq];
                float4 q0 = w0p[jq], q1 = w1p[jq], q2 = w2p[jq], q3 = w3p[jq];
                a0 = fmaf(q0.x,sv.x,a0); a0 = fmaf(q0.y,sv.y,a0); a0 = fmaf(q0.z,sv.z,a0); a0 = fmaf(q0.w,sv.w,a0);
                a1 = fmaf(q1.x,sv.x,a1); a1 = fmaf(q1.y,sv.y,a1); a1 = fmaf(q1.z,sv.z,a1); a1 = fmaf(q1.w,sv.w,a1);
                a2 = fmaf(q2.x,sv.x,a2); a2 = fmaf(q2.y,sv.y,a2); a2 = fmaf(q2.z,sv.z,a2); a2 = fmaf(q2.w,sv.w,a2);
                a3 = fmaf(q3.x,sv.x,a3); a3 = fmaf(q3.y,sv.y,a3); a3 = fmaf(q3.z,sv.z,a3); a3 = fmaf(q3.w,sv.w,a3);
            }
            size_t base = ((size_t)(b*Ov + ob)*Hv + h)*Wv + w0 + p;
            out[base]          = a0;
            out[base + HWv]    = a1;
            out[base + 2*HWv]  = a2;
            out[base + 3*HWv]  = a3;
        }
    }
}

// ---------------------------------------------------------------------------
// BN
// ---------------------------------------------------------------------------
__global__ void reduce_kernel(const float* __restrict__ y) {
    int c = blockIdx.x, b = blockIdx.y, tid = threadIdx.x;
    const float4* p = (const float4*)y + (size_t)(b*Ov + c)*4096;
    float s = 0.f, q = 0.f;
    for (int i = tid; i < 4096; i += 256) {
        float4 v = p[i];
        s += v.x + v.y + v.z + v.w;
        q = fmaf(v.x,v.x,q); q = fmaf(v.y,v.y,q); q = fmaf(v.z,v.z,q); q = fmaf(v.w,v.w,q);
    }
    __shared__ float ssum[8], ssq[8];
    #pragma unroll
    for (int o = 16; o > 0; o >>= 1) {
        s += __shfl_down_sync(0xffffffff, s, o);
        q += __shfl_down_sync(0xffffffff, q, o);
    }
    if ((tid & 31) == 0) { ssum[tid >> 5] = s; ssq[tid >> 5] = q; }
    __syncthreads();
    if (tid < 8) {
        s = ssum[tid]; q = ssq[tid];
        #pragma unroll
        for (int o = 4; o > 0; o >>= 1) {
            s += __shfl_down_sync(0xff, s, o);
            q += __shfl_down_sync(0xff, q, o);
        }
        if (tid == 0) { g_psum[c*Bv + b] = s; g_psq[c*Bv + b] = q; }
    }
}

__global__ void stats_kernel() {
    int c = threadIdx.x;
    float s = 0.f, q = 0.f;
    for (int b = 0; b < Bv; b++) { s += g_psum[c*Bv + b]; q += g_psq[c*Bv + b]; }
    const float inv = 1.f / (float)(Bv*HWv);
    float mean = s * inv;
    float var  = q * inv - mean*mean;
    g_mean[c] = mean;
    g_rstd[c] = rsqrtf(var + 1e-5f);
}

__global__ void bn_kernel(float* __restrict__ y,
                          const float* __restrict__ gamma,
                          const float* __restrict__ beta) {
    int idx = blockIdx.x*256 + threadIdx.x;
    if (idx >= Bv*Ov*HWv/4) return;
    int c = (idx >> 12) & 63;
    float a  = g_rstd[c] * gamma[c];
    float bb = fmaf(-g_mean[c], a, beta[c]);
    float4* p = (float4*)y;
    float4 v = p[idx];
    v.x = fmaxf(fmaf(v.x, a, bb), 0.f);
    v.y = fmaxf(fmaf(v.y, a, bb), 0.f);
    v.z = fmaxf(fmaf(v.z, a, bb), 0.f);
    v.w = fmaxf(fmaf(v.w, a, bb), 0.f);
    p[idx] = v;
}

// ---------------------------------------------------------------------------
extern "C" void kernel_launch(void* const* d_in, const int* in_sizes, int n_in,
                              void* d_out, int out_size) {
    const float* x     = (const float*)d_in[0];
    const float* wh    = (const float*)d_in[1];
    const float* bh    = (const float*)d_in[2];
    const float* wv    = (const float*)d_in[3];
    const float* bv    = (const float*)d_in[4];
    const float* wm    = (const float*)d_in[5];
    const float* bm    = (const float*)d_in[6];
    const float* wd    = (const float*)d_in[7];
    const float* gamma = (const float*)d_in[8];
    const float* beta  = (const float*)d_in[9];
    float* out = (float*)d_out;

    const int deform_smem = (64*SW_STRIDE + 16*SS_STRIDE + 288)*4 + 144*16;  // ~189 KB
    cudaFuncSetAttribute(deform_kernel, cudaFuncAttributeMaxDynamicSharedMemorySize, deform_smem);

    pack_kernel<<<(18432 + 6912 + 36864 + 255)/256, 256>>>(wh, wv, wm, wd);
    transpose_kernel<<<dim3(HWv/32, Cv/32, Bv), dim3(32, 8)>>>(x);
    offmask_kernel<<<dim3(Wv/32, Hv/8, Bv), 128>>>(x, bh, bv, bm);
    deform_kernel<<<1024, 256, deform_smem>>>(out);
    reduce_kernel<<<dim3(Ov, Bv), 256>>>(out);
    stats_kernel<<<1, Ov>>>();
    bn_kernel<<<(Bv*Ov*HWv/4 + 255)/256, 256>>>(out, gamma, beta);
}

// round 4
// speedup vs baseline: 3.6471x; 1.1478x over previous
#include <cuda_runtime.h>
#include <math.h>

#define Bv 8
#define Cv 64
#define Hv 128
#define Wv 128
#define Ov 64
#define HWv (Hv*Wv)

// scratch (__device__ globals; no allocation allowed)
__device__ float g_offset[Bv*18*HWv];   // (B,18,H,W)
__device__ float g_mask[Bv*9*HWv];      // (B,9,H,W)
__device__ float g_xt[(size_t)Bv*HWv*Cv]; // (B,H,W,C)
__device__ float g_whP[Cv*18*16];
__device__ float g_wvP[Cv*18*16];
__device__ float g_wmP[Cv*9*12];
__device__ float g_wdT[Ov*576];         // [o][k*64+c]
__device__ float g_psum[Ov*Bv];
__device__ float g_psq[Ov*Bv];
__device__ float g_mean[Ov];
__device__ float g_rstd[Ov];

// ---------------------------------------------------------------------------
// weight packer
// ---------------------------------------------------------------------------
__global__ void pack_kernel(const float* __restrict__ wh, const float* __restrict__ wv,
                            const float* __restrict__ wm, const float* __restrict__ wd) {
    int idx = blockIdx.x*256 + threadIdx.x;
    if (idx < 18432) {
        int c = idx/288, r = idx - c*288, o = r >> 4, k = r & 15;
        g_whP[idx] = (k < 15) ? wh[(o*Cv + c)*15 + k] : 0.f;
        g_wvP[idx] = (k < 15) ? wv[(o*Cv + c)*15 + k] : 0.f;
    } else if (idx < 18432 + 6912) {
        int j = idx - 18432;
        int c = j/108, r = j - c*108, o = r/12, k = r - o*12;
        g_wmP[j] = (k < 9) ? wm[(o*Cv + c)*9 + k] : 0.f;
    } else if (idx < 18432 + 6912 + 36864) {
        int j = idx - 18432 - 6912;
        int o = j/576, r = j - o*576, k = r >> 6, c = r & 63;
        g_wdT[j] = wd[(o*Cv + c)*9 + k];
    }
}

// ---------------------------------------------------------------------------
// x (B,C,HW) -> xt (B,HW,C)
// ---------------------------------------------------------------------------
__global__ void transpose_kernel(const float* __restrict__ x) {
    __shared__ float t[32][33];
    int b = blockIdx.z;
    int hw0 = blockIdx.x * 32;
    int c0  = blockIdx.y * 32;
    int tx = threadIdx.x, ty = threadIdx.y;
    #pragma unroll
    for (int j = 0; j < 4; j++) {
        int c = c0 + ty + j*8;
        t[ty + j*8][tx] = x[((size_t)b*Cv + c)*HWv + hw0 + tx];
    }
    __syncthreads();
    #pragma unroll
    for (int j = 0; j < 4; j++) {
        int hw = hw0 + ty + j*8;
        g_xt[((size_t)b*HWv + hw)*Cv + c0 + tx] = t[tx][ty + j*8];
    }
}

// ---------------------------------------------------------------------------
// fused offset(18ch) + mask(9ch), 32x8 tile, 128 threads, 2 px/thread
// double-buffered input tile, precomputed load slots, 1 barrier/channel
// ---------------------------------------------------------------------------
__global__ void __launch_bounds__(128, 3) offmask_kernel(
    const float* __restrict__ x,
    const float* __restrict__ bh, const float* __restrict__ bv,
    const float* __restrict__ bm)
{
    __shared__ float tiles[2][22*47];
    int b  = blockIdx.z;
    int h0 = blockIdx.y * 8;
    int wb = blockIdx.x * 32;
    int tid = threadIdx.x;
    int tx = tid & 15, ty = tid >> 4;
    int h = h0 + ty;
    int w = wb + 2*tx;

    // precompute 8 load slots per thread
    int  soff[8];   // global offset, or -1 if OOB/unused
    int  sidx[8];   // smem index
    #pragma unroll
    for (int s = 0; s < 8; s++) {
        int i = tid + s*128;
        if (i < 22*46) {
            int r = i / 46, cc = i - r*46;
            int gh = h0 + r - 7, gw = wb + cc - 7;
            sidx[s] = r*47 + cc;
            soff[s] = (gh >= 0 && gh < Hv && gw >= 0 && gw < Wv) ? gh*Wv + gw : -1;
        } else { sidx[s] = -1; soff[s] = -1; }
    }

    float acc0[18], acc1[18], am0[9], am1[9];
    #pragma unroll
    for (int o = 0; o < 18; o++) { float bo = bh[o] + bv[o]; acc0[o] = bo; acc1[o] = bo; }
    #pragma unroll
    for (int o = 0; o < 9; o++)  { float bo = bm[o]; am0[o] = bo; am1[o] = bo; }

    const float* xb = x + (size_t)b*Cv*HWv;

    // preload c=0
    {
        const float* xc = xb;
        #pragma unroll
        for (int s = 0; s < 8; s++)
            if (sidx[s] >= 0) tiles[0][sidx[s]] = (soff[s] >= 0) ? __ldg(xc + soff[s]) : 0.f;
    }

    for (int c = 0; c < Cv; c++) {
        __syncthreads();   // tiles[c&1] ready; prev reads of tiles[(c+1)&1] done
        if (c + 1 < Cv) {
            const float* xc = xb + (c+1)*HWv;
            float* dst = tiles[(c+1) & 1];
            #pragma unroll
            for (int s = 0; s < 8; s++)
                if (sidx[s] >= 0) dst[sidx[s]] = (soff[s] >= 0) ? __ldg(xc + soff[s]) : 0.f;
        }
        const float* tile = tiles[c & 1];

        float xr[16];
        #pragma unroll
        for (int i = 0; i < 16; i++) xr[i] = tile[(ty+7)*47 + 2*tx + i];
        float xcA[15], xcB[15];
        #pragma unroll
        for (int i = 0; i < 15; i++) {
            xcA[i] = tile[(ty+i)*47 + 2*tx + 7];
            xcB[i] = tile[(ty+i)*47 + 2*tx + 8];
        }
        float t00 = tile[(ty+6)*47 + 2*tx + 6];
        float t01 = tile[(ty+6)*47 + 2*tx + 9];
        float t10 = tile[(ty+8)*47 + 2*tx + 6];
        float t11 = tile[(ty+8)*47 + 2*tx + 9];

        const float4* whc = (const float4*)(g_whP + c*288);
        const float4* wvc = (const float4*)(g_wvP + c*288);
        const float4* wmc = (const float4*)(g_wmP + c*108);
        #pragma unroll
        for (int o = 0; o < 18; o++) {
            float4 q0 = whc[o*4+0], q1 = whc[o*4+1], q2 = whc[o*4+2], q3 = whc[o*4+3];
            float wkh[15] = {q0.x,q0.y,q0.z,q0.w, q1.x,q1.y,q1.z,q1.w,
                             q2.x,q2.y,q2.z,q2.w, q3.x,q3.y,q3.z};
            float a0 = acc0[o], a1 = acc1[o];
            #pragma unroll
            for (int k = 0; k < 15; k++) {
                a0 = fmaf(xr[k],   wkh[k], a0);
                a1 = fmaf(xr[k+1], wkh[k], a1);
            }
            float4 v0 = wvc[o*4+0], v1 = wvc[o*4+1], v2 = wvc[o*4+2], v3 = wvc[o*4+3];
            float wkv[15] = {v0.x,v0.y,v0.z,v0.w, v1.x,v1.y,v1.z,v1.w,
                             v2.x,v2.y,v2.z,v2.w, v3.x,v3.y,v3.z};
            #pragma unroll
            for (int k = 0; k < 15; k++) {
                a0 = fmaf(xcA[k], wkv[k], a0);
                a1 = fmaf(xcB[k], wkv[k], a1);
            }
            acc0[o] = a0; acc1[o] = a1;
        }
        #pragma unroll
        for (int o = 0; o < 9; o++) {
            float4 q0 = wmc[o*3], q1 = wmc[o*3+1], q2 = wmc[o*3+2];
            float m0 = am0[o], m1 = am1[o];
            m0 = fmaf(t00,    q0.x, m0);  m1 = fmaf(xcA[6], q0.x, m1);
            m0 = fmaf(xcA[6], q0.y, m0);  m1 = fmaf(xcB[6], q0.y, m1);
            m0 = fmaf(xcB[6], q0.z, m0);  m1 = fmaf(t01,    q0.z, m1);
            m0 = fmaf(xr[6],  q0.w, m0);  m1 = fmaf(xr[7],  q0.w, m1);
            m0 = fmaf(xr[7],  q1.x, m0);  m1 = fmaf(xr[8],  q1.x, m1);
            m0 = fmaf(xr[8],  q1.y, m0);  m1 = fmaf(xr[9],  q1.y, m1);
            m0 = fmaf(t10,    q1.z, m0);  m1 = fmaf(xcA[8], q1.z, m1);
            m0 = fmaf(xcA[8], q1.w, m0);  m1 = fmaf(xcB[8], q1.w, m1);
            m0 = fmaf(xcB[8], q2.x, m0);  m1 = fmaf(t11,    q2.x, m1);
            am0[o] = m0; am1[o] = m1;
        }
    }

    #pragma unroll
    for (int o = 0; o < 18; o++) {
        float2 v; v.x = acc0[o]; v.y = acc1[o];
        *(float2*)&g_offset[((b*18 + o)*Hv + h)*Wv + w] = v;
    }
    #pragma unroll
    for (int o = 0; o < 9; o++) {
        float2 v;
        v.x = 1.f/(1.f + __expf(-am0[o]));
        v.y = 1.f/(1.f + __expf(-am1[o]));
        *(float2*)&g_mask[((b*9 + o)*Hv + h)*Wv + w] = v;
    }
}

// ---------------------------------------------------------------------------
// deform: 16-pixel tile; stage A interp setup; stage B HWC gather -> ss;
// stage C: 4o x 4p x Ksplit-4 register tiling + smem reduction (FMA-bound)
// ---------------------------------------------------------------------------
#define SW_STRIDE 608
#define SW_FLOATS 38912          // 63*608 + 28 + 576 = 38908, rounded
#define SS_STRIDE 580
// float offsets inside dynamic smem
#define OFF_SS   SW_FLOATS                        // 16*580 = 9280
#define OFF_RED  (OFF_SS + 16*SS_STRIDE)          // 4096
#define OFF_SAY  (OFF_RED + 4096)                 // 144
#define OFF_SAX  (OFF_SAY + 144)                  // 144
#define OFF_SAW  (OFF_SAX + 144)                  // 144 float4 = 576 floats
#define SMEM_FLOATS (OFF_SAW + 576)

__device__ __forceinline__ int wrow_off(int o) {
    return o*SW_STRIDE + ((o >> 2) & 7)*4;   // 16B skew per o-group -> bank spread
}

__global__ void __launch_bounds__(256, 1) deform_kernel(float* __restrict__ out) {
    extern __shared__ float smem[];
    float* sw  = smem;
    float* ss  = smem + OFF_SS;
    float* red = smem + OFF_RED;
    int*  sAy  = (int*)(smem + OFF_SAY);
    int*  sAx  = (int*)(smem + OFF_SAX);
    float4* sAw = (float4*)(smem + OFF_SAW);
    int tid = threadIdx.x;

    // load weights with skewed row layout
    const float4* wt4 = (const float4*)g_wdT;
    for (int i = tid; i < 64*144; i += 256) {
        int o = i / 144, q = i - o*144;
        ((float4*)(sw + wrow_off(o)))[q] = wt4[i];
    }

    int h  = blockIdx.x >> 3;
    int w0 = (blockIdx.x & 7) << 4;

    // stage C thread mapping
    int og = tid & 15;            // o-group: o = og*4 + oi
    int pg = (tid >> 4) & 3;      // pixel-group: p = pg*4 + pp
    int ks = tid >> 6;            // K slice: q = ks*36 .. +35
    const float* wbase = sw + wrow_off(og*4);
    const float4* w0p = (const float4*)(wbase)               + ks*36;
    const float4* w1p = (const float4*)(wbase + SW_STRIDE)   + ks*36;
    const float4* w2p = (const float4*)(wbase + 2*SW_STRIDE) + ks*36;
    const float4* w3p = (const float4*)(wbase + 3*SW_STRIDE) + ks*36;
    const float4* p0p = (const float4*)(ss + (pg*4+0)*SS_STRIDE) + ks*36;
    const float4* p1p = (const float4*)(ss + (pg*4+1)*SS_STRIDE) + ks*36;
    const float4* p2p = (const float4*)(ss + (pg*4+2)*SS_STRIDE) + ks*36;
    const float4* p3p = (const float4*)(ss + (pg*4+3)*SS_STRIDE) + ks*36;

    // reducer mapping
    int rg = tid & 63, half = tid >> 6;
    int r_og = rg & 15, r_pg = rg >> 4;
    int r_o = r_og*4 + half;
    int r_p = r_pg*4;

    for (int b = 0; b < Bv; b++) {
        __syncthreads();   // weights/prev reduce done
        if (tid < 144) {
            int p = tid / 9, k = tid - p*9;
            int w = w0 + p;
            int ky = k / 3, kx = k - ky*3;
            float dy = g_offset[((b*18 + 2*k    )*Hv + h)*Wv + w];
            float dx = g_offset[((b*18 + 2*k + 1)*Hv + h)*Wv + w];
            float m  = g_mask  [((b*9  + k      )*Hv + h)*Wv + w];
            float py = (float)(h + ky - 1) + dy;
            float px = (float)(w + kx - 1) + dx;
            float y0f = floorf(py), x0f = floorf(px);
            float wy1 = py - y0f, wx1 = px - x0f;
            float wy0 = 1.f - wy1, wx0 = 1.f - wx1;
            int iy0 = (int)y0f, ix0 = (int)x0f;
            bool vy0 = (iy0 >= 0)  && (iy0 < Hv);
            bool vy1 = (iy0 >= -1) && (iy0 < Hv-1);
            bool vx0 = (ix0 >= 0)  && (ix0 < Wv);
            bool vx1 = (ix0 >= -1) && (ix0 < Wv-1);
            sAy[tid] = iy0; sAx[tid] = ix0;
            sAw[tid] = make_float4((vy0 && vx0) ? m*wy0*wx0 : 0.f,
                                   (vy0 && vx1) ? m*wy0*wx1 : 0.f,
                                   (vy1 && vx0) ? m*wy1*wx0 : 0.f,
                                   (vy1 && vx1) ? m*wy1*wx1 : 0.f);
        }
        __syncthreads();

        const float4* xb4 = (const float4*)g_xt + (size_t)b*HWv*16;
        #pragma unroll
        for (int itb = 0; itb < 9; itb++) {
            int it = itb*256 + tid;       // 0..2303
            int pk = it >> 4, cq = it & 15;
            int iy0 = sAy[pk], ix0 = sAx[pk];
            float4 wg = sAw[pk];
            int y0c = min(Hv-1, max(0, iy0));
            int y1c = min(Hv-1, max(0, iy0 + 1));
            int x0c = min(Wv-1, max(0, ix0));
            int x1c = min(Wv-1, max(0, ix0 + 1));
            float4 v00 = xb4[(y0c*Wv + x0c)*16 + cq];
            float4 v01 = xb4[(y0c*Wv + x1c)*16 + cq];
            float4 v10 = xb4[(y1c*Wv + x0c)*16 + cq];
            float4 v11 = xb4[(y1c*Wv + x1c)*16 + cq];
            float4 r;
            r.x = fmaf(wg.w, v11.x, fmaf(wg.z, v10.x, fmaf(wg.y, v01.x, wg.x*v00.x)));
            r.y = fmaf(wg.w, v11.y, fmaf(wg.z, v10.y, fmaf(wg.y, v01.y, wg.x*v00.y)));
            r.z = fmaf(wg.w, v11.z, fmaf(wg.z, v10.z, fmaf(wg.y, v01.z, wg.x*v00.z)));
            r.w = fmaf(wg.w, v11.w, fmaf(wg.z, v10.w, fmaf(wg.y, v01.w, wg.x*v00.w)));
            int p = pk / 9, k = pk - p*9;
            ((float4*)(ss + p*SS_STRIDE))[k*16 + cq] = r;
        }
        __syncthreads();

        // stage C: 16 accumulators (4 o x 4 p), 36 K-chunks of 4
        float a00=0,a01=0,a02=0,a03=0, a10=0,a11=0,a12=0,a13=0;
        float a20=0,a21=0,a22=0,a23=0, a30=0,a31=0,a32=0,a33=0;
        #pragma unroll 4
        for (int q = 0; q < 36; q++) {
            float4 qa = w0p[q], qb = w1p[q], qc = w2p[q], qd = w3p[q];
            float4 s0 = p0p[q], s1 = p1p[q], s2 = p2p[q], s3 = p3p[q];
            a00=fmaf(qa.x,s0.x,a00); a00=fmaf(qa.y,s0.y,a00); a00=fmaf(qa.z,s0.z,a00); a00=fmaf(qa.w,s0.w,a00);
            a01=fmaf(qa.x,s1.x,a01); a01=fmaf(qa.y,s1.y,a01); a01=fmaf(qa.z,s1.z,a01); a01=fmaf(qa.w,s1.w,a01);
            a02=fmaf(qa.x,s2.x,a02); a02=fmaf(qa.y,s2.y,a02); a02=fmaf(qa.z,s2.z,a02); a02=fmaf(qa.w,s2.w,a02);
            a03=fmaf(qa.x,s3.x,a03); a03=fmaf(qa.y,s3.y,a03); a03=fmaf(qa.z,s3.z,a03); a03=fmaf(qa.w,s3.w,a03);
            a10=fmaf(qb.x,s0.x,a10); a10=fmaf(qb.y,s0.y,a10); a10=fmaf(qb.z,s0.z,a10); a10=fmaf(qb.w,s0.w,a10);
            a11=fmaf(qb.x,s1.x,a11); a11=fmaf(qb.y,s1.y,a11); a11=fmaf(qb.z,s1.z,a11); a11=fmaf(qb.w,s1.w,a11);
            a12=fmaf(qb.x,s2.x,a12); a12=fmaf(qb.y,s2.y,a12); a12=fmaf(qb.z,s2.z,a12); a12=fmaf(qb.w,s2.w,a12);
            a13=fmaf(qb.x,s3.x,a13); a13=fmaf(qb.y,s3.y,a13); a13=fmaf(qb.z,s3.z,a13); a13=fmaf(qb.w,s3.w,a13);
            a20=fmaf(qc.x,s0.x,a20); a20=fmaf(qc.y,s0.y,a20); a20=fmaf(qc.z,s0.z,a20); a20=fmaf(qc.w,s0.w,a20);
            a21=fmaf(qc.x,s1.x,a21); a21=fmaf(qc.y,s1.y,a21); a21=fmaf(qc.z,s1.z,a21); a21=fmaf(qc.w,s1.w,a21);
            a22=fmaf(qc.x,s2.x,a22); a22=fmaf(qc.y,s2.y,a22); a22=fmaf(qc.z,s2.z,a22); a22=fmaf(qc.w,s2.w,a22);
            a23=fmaf(qc.x,s3.x,a23); a23=fmaf(qc.y,s3.y,a23); a23=fmaf(qc.z,s3.z,a23); a23=fmaf(qc.w,s3.w,a23);
            a30=fmaf(qd.x,s0.x,a30); a30=fmaf(qd.y,s0.y,a30); a30=fmaf(qd.z,s0.z,a30); a30=fmaf(qd.w,s0.w,a30);
            a31=fmaf(qd.x,s1.x,a31); a31=fmaf(qd.y,s1.y,a31); a31=fmaf(qd.z,s1.z,a31); a31=fmaf(qd.w,s1.w,a31);
            a32=fmaf(qd.x,s2.x,a32); a32=fmaf(qd.y,s2.y,a32); a32=fmaf(qd.z,s2.z,a32); a32=fmaf(qd.w,s2.w,a32);
            a33=fmaf(qd.x,s3.x,a33); a33=fmaf(qd.y,s3.y,a33); a33=fmaf(qd.z,s3.z,a33); a33=fmaf(qd.w,s3.w,a33);
        }
        // write partials: red[ks*1024 + rg*16 + oi*4 + pp]
        {
            float4* rp = (float4*)(red + ks*1024 + (tid & 63)*16);
            rp[0] = make_float4(a00,a01,a02,a03);
            rp[1] = make_float4(a10,a11,a12,a13);
            rp[2] = make_float4(a20,a21,a22,a23);
            rp[3] = make_float4(a30,a31,a32,a33);
        }
        __syncthreads();

        // reduce 4 K-slices -> output float4 (o = r_o, pixels r_p..r_p+3)
        {
            const float4* r4 = (const float4*)red;
            int base = rg*4 + half;       // float4 index within a slice
            float4 v0 = r4[base];
            float4 v1 = r4[256 + base];
            float4 v2 = r4[512 + base];
            float4 v3 = r4[768 + base];
            float4 res;
            res.x = (v0.x+v1.x) + (v2.x+v3.x);
            res.y = (v0.y+v1.y) + (v2.y+v3.y);
            res.z = (v0.z+v1.z) + (v2.z+v3.z);
            res.w = (v0.w+v1.w) + (v2.w+v3.w);
            *(float4*)&out[((size_t)(b*Ov + r_o)*Hv + h)*Wv + w0 + r_p] = res;
        }
    }
}

// ---------------------------------------------------------------------------
// BN
// ---------------------------------------------------------------------------
__global__ void reduce_kernel(const float* __restrict__ y) {
    int c = blockIdx.x, b = blockIdx.y, tid = threadIdx.x;
    const float4* p = (const float4*)y + (size_t)(b*Ov + c)*4096;
    float s = 0.f, q = 0.f;
    for (int i = tid; i < 4096; i += 256) {
        float4 v = p[i];
        s += v.x + v.y + v.z + v.w;
        q = fmaf(v.x,v.x,q); q = fmaf(v.y,v.y,q); q = fmaf(v.z,v.z,q); q = fmaf(v.w,v.w,q);
    }
    __shared__ float ssum[8], ssq[8];
    #pragma unroll
    for (int o = 16; o > 0; o >>= 1) {
        s += __shfl_down_sync(0xffffffff, s, o);
        q += __shfl_down_sync(0xffffffff, q, o);
    }
    if ((tid & 31) == 0) { ssum[tid >> 5] = s; ssq[tid >> 5] = q; }
    __syncthreads();
    if (tid < 8) {
        s = ssum[tid]; q = ssq[tid];
        #pragma unroll
        for (int o = 4; o > 0; o >>= 1) {
            s += __shfl_down_sync(0xff, s, o);
            q += __shfl_down_sync(0xff, q, o);
        }
        if (tid == 0) { g_psum[c*Bv + b] = s; g_psq[c*Bv + b] = q; }
    }
}

__global__ void stats_kernel() {
    int c = threadIdx.x;
    float s = 0.f, q = 0.f;
    for (int b = 0; b < Bv; b++) { s += g_psum[c*Bv + b]; q += g_psq[c*Bv + b]; }
    const float inv = 1.f / (float)(Bv*HWv);
    float mean = s * inv;
    float var  = q * inv - mean*mean;
    g_mean[c] = mean;
    g_rstd[c] = rsqrtf(var + 1e-5f);
}

__global__ void bn_kernel(float* __restrict__ y,
                          const float* __restrict__ gamma,
                          const float* __restrict__ beta) {
    int idx = blockIdx.x*256 + threadIdx.x;
    if (idx >= Bv*Ov*HWv/4) return;
    int c = (idx >> 12) & 63;
    float a  = g_rstd[c] * gamma[c];
    float bb = fmaf(-g_mean[c], a, beta[c]);
    float4* p = (float4*)y;
    float4 v = p[idx];
    v.x = fmaxf(fmaf(v.x, a, bb), 0.f);
    v.y = fmaxf(fmaf(v.y, a, bb), 0.f);
    v.z = fmaxf(fmaf(v.z, a, bb), 0.f);
    v.w = fmaxf(fmaf(v.w, a, bb), 0.f);
    p[idx] = v;
}

// ---------------------------------------------------------------------------
extern "C" void kernel_launch(void* const* d_in, const int* in_sizes, int n_in,
                              void* d_out, int out_size) {
    const float* x     = (const float*)d_in[0];
    const float* wh    = (const float*)d_in[1];
    const float* bh    = (const float*)d_in[2];
    const float* wv    = (const float*)d_in[3];
    const float* bv    = (const float*)d_in[4];
    const float* wm    = (const float*)d_in[5];
    const float* bm    = (const float*)d_in[6];
    const float* wd    = (const float*)d_in[7];
    const float* gamma = (const float*)d_in[8];
    const float* beta  = (const float*)d_in[9];
    float* out = (float*)d_out;

    const int deform_smem = SMEM_FLOATS * 4;   // ~212.6 KB
    cudaFuncSetAttribute(deform_kernel, cudaFuncAttributeMaxDynamicSharedMemorySize, deform_smem);

    pack_kernel<<<(18432 + 6912 + 36864 + 255)/256, 256>>>(wh, wv, wm, wd);
    transpose_kernel<<<dim3(HWv/32, Cv/32, Bv), dim3(32, 8)>>>(x);
    offmask_kernel<<<dim3(Wv/32, Hv/8, Bv), 128>>>(x, bh, bv, bm);
    deform_kernel<<<1024, 256, deform_smem>>>(out);
    reduce_kernel<<<dim3(Ov, Bv), 256>>>(out);
    stats_kernel<<<1, Ov>>>();
    bn_kernel<<<(Bv*Ov*HWv/4 + 255)/256, 256>>>(out, gamma, beta);
}